// round 4
// baseline (speedup 1.0000x reference)
#include <cuda_runtime.h>
#include <cuda_bf16.h>
#include <cstdint>

// ----------------------------------------------------------------------------
// y[M,N] = x[M,K] @ A[N,K]^T,  M=65536, K=512, N=512, fp32 in/out.
// Baseline sm_100 target (no tcgen05/wgmma): mma.sync.m16n8k16 bf16, fp32 acc.
// Ootomo split: x = xh + xl, w = wh + wl (bf16); y ≈ xh*wh + xh*wl + xl*wh.
// x split is FUSED into the GEMM (register-staged f32 -> bf16 hi/lo -> SMEM).
// Only w (1 MB) is pre-split into small device-global scratch.
// ----------------------------------------------------------------------------

#define M_TOTAL   65536
#define K_DIM     512
#define N_DIM     512

#define MT        128           // M tile per CTA
#define NT        128           // N tile per CTA
#define KC        64            // K chunk (bf16 elems) = 128B rows (SW128)
#define NCHUNK    (K_DIM / KC)  // 8

#define TILE_SZ      (128u * 128u)      // 128 rows x 64 bf16 = 16384 B
#define STAGE_BYTES  (4u * TILE_SZ)     // XH, XL, WH, WL = 65536 B
#define SMEM_BYTES   (2u * STAGE_BYTES) // double buffered = 131072 B

// ---------------------------- small scratch (w split only) ------------------
__device__ __align__(16) __nv_bfloat16 g_whi[(size_t)N_DIM * K_DIM];  // 512 KB
__device__ __align__(16) __nv_bfloat16 g_wlo[(size_t)N_DIM * K_DIM];  // 512 KB

// ---------------------------- PTX helpers -----------------------------------
__device__ __forceinline__ uint32_t smem_u32(const void* p) {
    uint32_t a;
    asm("{ .reg .u64 t; cvta.to.shared.u64 t, %1; cvt.u32.u64 %0, t; }"
        : "=r"(a) : "l"(p));
    return a;
}

__device__ __forceinline__ void cp16(uint32_t dst, const void* src) {
    asm volatile("cp.async.cg.shared.global [%0], [%1], 16;"
                 :: "r"(dst), "l"(src) : "memory");
}
#define CP_COMMIT() asm volatile("cp.async.commit_group;" ::: "memory")

__device__ __forceinline__ void ldsm_x4(uint32_t addr, uint32_t& r0,
                                        uint32_t& r1, uint32_t& r2,
                                        uint32_t& r3) {
    asm volatile("ldmatrix.sync.aligned.m8n8.x4.shared.b16 {%0,%1,%2,%3}, [%4];"
                 : "=r"(r0), "=r"(r1), "=r"(r2), "=r"(r3) : "r"(addr));
}

__device__ __forceinline__ void mma16816(float* d, const uint32_t* a,
                                         const uint32_t* b) {
    asm volatile(
        "mma.sync.aligned.m16n8k16.row.col.f32.bf16.bf16.f32 "
        "{%0,%1,%2,%3}, {%4,%5,%6,%7}, {%8,%9}, {%0,%1,%2,%3};"
        : "+f"(d[0]), "+f"(d[1]), "+f"(d[2]), "+f"(d[3])
        : "r"(a[0]), "r"(a[1]), "r"(a[2]), "r"(a[3]), "r"(b[0]), "r"(b[1]));
}

__device__ __forceinline__ void sts16(uint32_t addr, uint4 v) {
    asm volatile("st.shared.v4.b32 [%0], {%1,%2,%3,%4};"
                 :: "r"(addr), "r"(v.x), "r"(v.y), "r"(v.z), "r"(v.w));
}

// split one f32 into bf16 hi + bf16 lo (returned as ushorts)
__device__ __forceinline__ void split1(float f, unsigned& h, unsigned& l) {
    __nv_bfloat16 hb = __float2bfloat16(f);
    float r = f - __bfloat162float(hb);
    __nv_bfloat16 lb = __float2bfloat16(r);
    h = (unsigned)__bfloat16_as_ushort(hb);
    l = (unsigned)__bfloat16_as_ushort(lb);
}

// ---------------------------- w split kernel --------------------------------
__global__ void split_w_kernel(const float4* __restrict__ w4) {
    uint2* oh = reinterpret_cast<uint2*>(g_whi);
    uint2* ol = reinterpret_cast<uint2*>(g_wlo);
    const int n4 = (N_DIM * K_DIM) / 4;
    for (int i = blockIdx.x * blockDim.x + threadIdx.x; i < n4;
         i += gridDim.x * blockDim.x) {
        float4 v = w4[i];
        const float* f = (const float*)&v;
        unsigned hs[4], ls[4];
#pragma unroll
        for (int k = 0; k < 4; k++) split1(f[k], hs[k], ls[k]);
        oh[i] = make_uint2(hs[0] | (hs[1] << 16), hs[2] | (hs[3] << 16));
        ol[i] = make_uint2(ls[0] | (ls[1] << 16), ls[2] | (ls[3] << 16));
    }
}

// ---------------------------- GEMM kernel -----------------------------------
// Per-stage SMEM: XH(16K) XL(16K) WH(16K) WL(16K); SW128 swizzle per tile:
// byte = row*128 + ((c16 ^ (row&7)) << 4), row = m-or-n row, c16 = 16B chunk.

// W tiles for chunk kc -> stage s (cp.async, bf16 from scratch)
__device__ __forceinline__ void load_w(uint32_t sbase, int s, int kc,
                                       int n_base, int tid) {
    const uint32_t base = sbase + (uint32_t)s * STAGE_BYTES + 2u * TILE_SZ;
    const int kcol = kc * KC;
#pragma unroll
    for (int i = 0; i < 4; i++) {          // 1024 chunks / 256 threads
        int idx = tid + i * 256;
        int row = idx >> 3, c16 = idx & 7;
        uint32_t d0 = base + (uint32_t)row * 128u +
                      (uint32_t)((c16 ^ (row & 7)) << 4);
        size_t off = (size_t)(n_base + row) * K_DIM + kcol + c16 * 8;
        cp16(d0, g_whi + off);
        cp16(d0 + TILE_SZ, g_wlo + off);
    }
}

// issue x f32 loads for chunk kc into regs (8 float4 per thread)
__device__ __forceinline__ void ldg_x(const float* __restrict__ x, int kc,
                                      int m_base, int tid, float4 xf[4][2]) {
    const int kcol = kc * KC;
#pragma unroll
    for (int i = 0; i < 4; i++) {
        int idx = tid + i * 256;
        int row = idx >> 3, c16 = idx & 7;
        const float* p = x + (size_t)(m_base + row) * K_DIM + kcol + c16 * 8;
        xf[i][0] = *reinterpret_cast<const float4*>(p);
        xf[i][1] = *reinterpret_cast<const float4*>(p + 4);
    }
}

// convert regs -> bf16 hi/lo, store to stage s x tiles
__device__ __forceinline__ void store_x(uint32_t sbase, int s, int tid,
                                        const float4 xf[4][2]) {
    const uint32_t xh = sbase + (uint32_t)s * STAGE_BYTES;
#pragma unroll
    for (int i = 0; i < 4; i++) {
        int idx = tid + i * 256;
        int row = idx >> 3, c16 = idx & 7;
        const float* f = (const float*)&xf[i][0];
        unsigned hs[8], ls[8];
#pragma unroll
        for (int k = 0; k < 8; k++) split1(f[k], hs[k], ls[k]);
        uint4 hv = make_uint4(hs[0] | (hs[1] << 16), hs[2] | (hs[3] << 16),
                              hs[4] | (hs[5] << 16), hs[6] | (hs[7] << 16));
        uint4 lv = make_uint4(ls[0] | (ls[1] << 16), ls[2] | (ls[3] << 16),
                              ls[4] | (ls[5] << 16), ls[6] | (ls[7] << 16));
        uint32_t d0 = xh + (uint32_t)row * 128u +
                      (uint32_t)((c16 ^ (row & 7)) << 4);
        sts16(d0, hv);
        sts16(d0 + TILE_SZ, lv);
    }
}

__global__ void __launch_bounds__(256, 1)
gemm_bf16x3_kernel(const float* __restrict__ x, float* __restrict__ y) {
    extern __shared__ char smem[];
    const uint32_t sbase = smem_u32(smem);
    const int tid = threadIdx.x;
    const int wid = tid >> 5;
    const int lid = tid & 31;
    const int m_base = blockIdx.y * MT;
    const int n_base = blockIdx.x * NT;

    const int wm = wid >> 1;   // warp -> 32 M rows
    const int wn = wid & 1;    // warp -> 64 N cols

    float acc[2][8][4];
#pragma unroll
    for (int mt = 0; mt < 2; mt++)
#pragma unroll
        for (int nt = 0; nt < 8; nt++)
#pragma unroll
            for (int j = 0; j < 4; j++) acc[mt][nt][j] = 0.f;

    // ldmatrix lane addressing (verified vs PTX mma fragment layouts):
    // A: lanes 0-7 rows0-7/kseg0, 8-15 rows8-15/kseg0, 16-23 rows0-7/kseg1,
    //    24-31 rows8-15/kseg1  -> r0..r3 = a0..a3 of m16n8k16.
    const int a_row = wm * 32 + (lid & 15);
    const int a_ks = lid >> 4;
    // B: lanes 0-7 n0-7/kseg0, 8-15 n0-7/kseg1, 16-23 n8-15/kseg0,
    //    24-31 n8-15/kseg1 -> r0,r1 = b0,b1 (even n8), r2,r3 (odd n8).
    const int b_row = wn * 64 + ((lid >> 4) << 3) + (lid & 7);
    const int b_ks = (lid >> 3) & 1;

    float4 xf[4][2];

    // ---- prologue: chunk 0 ----
    ldg_x(x, 0, m_base, tid, xf);
    store_x(sbase, 0, tid, xf);
    load_w(sbase, 0, 0, n_base, tid);
    CP_COMMIT();

#pragma unroll 1
    for (int c = 0; c < NCHUNK; c++) {
        const int s = c & 1;
        if (c + 1 < NCHUNK) {
            ldg_x(x, c + 1, m_base, tid, xf);      // long-latency, consumed late
            load_w(sbase, s ^ 1, c + 1, n_base, tid);
            CP_COMMIT();
            asm volatile("cp.async.wait_group 1;" ::: "memory");
        } else {
            asm volatile("cp.async.wait_group 0;" ::: "memory");
        }
        __syncthreads();    // stage s (x stores + w cp.async) visible to all

        const uint32_t xh = sbase + (uint32_t)s * STAGE_BYTES;
        const uint32_t xl = xh + TILE_SZ;
        const uint32_t wh = xh + 2u * TILE_SZ;
        const uint32_t wl = xh + 3u * TILE_SZ;

#pragma unroll
        for (int ks = 0; ks < 4; ks++) {           // K=16 per step
            uint32_t ah[2][4], al[2][4], bh[8][2], bl[8][2];
#pragma unroll
            for (int mt = 0; mt < 2; mt++) {
                int r = a_row + mt * 16;
                int c16 = ks * 2 + a_ks;
                uint32_t off = (uint32_t)r * 128u +
                               (uint32_t)((c16 ^ (r & 7)) << 4);
                ldsm_x4(xh + off, ah[mt][0], ah[mt][1], ah[mt][2], ah[mt][3]);
                ldsm_x4(xl + off, al[mt][0], al[mt][1], al[mt][2], al[mt][3]);
            }
#pragma unroll
            for (int bt = 0; bt < 4; bt++) {
                int r = b_row + bt * 16;
                int c16 = ks * 2 + b_ks;
                uint32_t off = (uint32_t)r * 128u +
                               (uint32_t)((c16 ^ (r & 7)) << 4);
                ldsm_x4(wh + off, bh[2 * bt][0], bh[2 * bt][1],
                        bh[2 * bt + 1][0], bh[2 * bt + 1][1]);
                ldsm_x4(wl + off, bl[2 * bt][0], bl[2 * bt][1],
                        bl[2 * bt + 1][0], bl[2 * bt + 1][1]);
            }
#pragma unroll
            for (int mt = 0; mt < 2; mt++)
#pragma unroll
                for (int nt = 0; nt < 8; nt++)
                    mma16816(acc[mt][nt], ah[mt], bh[nt]);   // hh
#pragma unroll
            for (int mt = 0; mt < 2; mt++)
#pragma unroll
                for (int nt = 0; nt < 8; nt++)
                    mma16816(acc[mt][nt], ah[mt], bl[nt]);   // hl
#pragma unroll
            for (int mt = 0; mt < 2; mt++)
#pragma unroll
                for (int nt = 0; nt < 8; nt++)
                    mma16816(acc[mt][nt], al[mt], bh[nt]);   // lh
        }

        if (c + 1 < NCHUNK) store_x(sbase, s ^ 1, tid, xf);  // convert + stage
        __syncthreads();    // stage s free for next prefetch; s^1 x complete
    }

    // ---- epilogue: direct float2 stores ----
    const int mrow0 = m_base + wm * 32 + (lid >> 2);
    const int ncol0 = n_base + wn * 64 + (lid & 3) * 2;
#pragma unroll
    for (int mt = 0; mt < 2; mt++) {
#pragma unroll
        for (int nt = 0; nt < 8; nt++) {
            float2 v0 = make_float2(acc[mt][nt][0], acc[mt][nt][1]);
            float2 v1 = make_float2(acc[mt][nt][2], acc[mt][nt][3]);
            size_t r0 = (size_t)(mrow0 + mt * 16) * N_DIM + ncol0 + nt * 8;
            size_t r1 = (size_t)(mrow0 + mt * 16 + 8) * N_DIM + ncol0 + nt * 8;
            *reinterpret_cast<float2*>(&y[r0]) = v0;
            *reinterpret_cast<float2*>(&y[r1]) = v1;
        }
    }
}

// ---------------------------- launch ----------------------------------------
extern "C" void kernel_launch(void* const* d_in, const int* in_sizes, int n_in,
                              void* d_out, int out_size) {
    const float* x = (const float*)d_in[0];   // 65536 x 512 f32
    const float* w = (const float*)d_in[1];   // 512 x 512 f32 (row-major A)
    float* y = (float*)d_out;

    cudaFuncSetAttribute(gemm_bf16x3_kernel,
                         cudaFuncAttributeMaxDynamicSharedMemorySize,
                         (int)SMEM_BYTES);

    split_w_kernel<<<64, 256>>>(reinterpret_cast<const float4*>(w));

    dim3 grid(N_DIM / NT, M_TOTAL / MT);  // (4, 512)
    gemm_bf16x3_kernel<<<grid, 256, SMEM_BYTES>>>(x, y);
}

// round 7
// speedup vs baseline: 1.0989x; 1.0989x over previous
#include <cuda_runtime.h>
#include <cuda_bf16.h>
#include <cstdint>

// ----------------------------------------------------------------------------
// y[M,N] = x[M,K] @ A[N,K]^T,  M=65536, K=512, N=512, fp32 in/out.
// Baseline sm_100 target: mma.sync.m16n8k16 bf16, fp32 acc.
// Ootomo split: x = xh + xl, w = wh + wl; y ≈ xh*wh + xh*wl + xl*wh.
// x split fused into GEMM. 2-stage smem ring, SINGLE sync per K-chunk:
//   reads of stage f=s^1 all occur in iteration c-1 before its end barrier;
//   iteration c's fills of f (cp.async + mid-MMA store_x) occur after it.
// ----------------------------------------------------------------------------

#define M_TOTAL   65536
#define K_DIM     512
#define N_DIM     512

#define MT        128           // M tile per CTA
#define NT        128           // N tile per CTA
#define KC        64            // K chunk (bf16 elems) = 128B rows (SW128)
#define NCHUNK    (K_DIM / KC)  // 8

#define TILE_SZ      (128u * 128u)      // 128 rows x 64 bf16 = 16384 B
#define STAGE_BYTES  (4u * TILE_SZ)     // XH, XL, WH, WL = 65536 B
#define SMEM_BYTES   (2u * STAGE_BYTES) // 131072 B (same as passing R4)

// ---------------------------- small scratch (w split only) ------------------
__device__ __align__(16) __nv_bfloat16 g_whi[(size_t)N_DIM * K_DIM];  // 512 KB
__device__ __align__(16) __nv_bfloat16 g_wlo[(size_t)N_DIM * K_DIM];  // 512 KB

// ---------------------------- PTX helpers -----------------------------------
__device__ __forceinline__ uint32_t smem_u32(const void* p) {
    uint32_t a;
    asm("{ .reg .u64 t; cvta.to.shared.u64 t, %1; cvt.u32.u64 %0, t; }"
        : "=r"(a) : "l"(p));
    return a;
}

__device__ __forceinline__ void cp16(uint32_t dst, const void* src) {
    asm volatile("cp.async.cg.shared.global [%0], [%1], 16;"
                 :: "r"(dst), "l"(src) : "memory");
}
#define CP_COMMIT() asm volatile("cp.async.commit_group;" ::: "memory")

__device__ __forceinline__ void ldsm_x4(uint32_t addr, uint32_t& r0,
                                        uint32_t& r1, uint32_t& r2,
                                        uint32_t& r3) {
    asm volatile("ldmatrix.sync.aligned.m8n8.x4.shared.b16 {%0,%1,%2,%3}, [%4];"
                 : "=r"(r0), "=r"(r1), "=r"(r2), "=r"(r3) : "r"(addr));
}

__device__ __forceinline__ void mma16816(float* d, const uint32_t* a,
                                         const uint32_t* b) {
    asm volatile(
        "mma.sync.aligned.m16n8k16.row.col.f32.bf16.bf16.f32 "
        "{%0,%1,%2,%3}, {%4,%5,%6,%7}, {%8,%9}, {%0,%1,%2,%3};"
        : "+f"(d[0]), "+f"(d[1]), "+f"(d[2]), "+f"(d[3])
        : "r"(a[0]), "r"(a[1]), "r"(a[2]), "r"(a[3]), "r"(b[0]), "r"(b[1]));
}

__device__ __forceinline__ void sts16(uint32_t addr, uint4 v) {
    asm volatile("st.shared.v4.b32 [%0], {%1,%2,%3,%4};"
                 :: "r"(addr), "r"(v.x), "r"(v.y), "r"(v.z), "r"(v.w));
}

// pack two f32 -> bf16x2 (RN); f0 in low halfword, f1 in high
__device__ __forceinline__ uint32_t cvt_bf16x2(float f0, float f1) {
    uint32_t r;
    asm("cvt.rn.bf16x2.f32 %0, %1, %2;" : "=r"(r) : "f"(f1), "f"(f0));
    return r;
}

// split a pair of f32 into packed hi bf16x2 and lo bf16x2
__device__ __forceinline__ void split_pair(float f0, float f1,
                                           uint32_t& hp, uint32_t& lp) {
    hp = cvt_bf16x2(f0, f1);
    float h0 = __uint_as_float(hp << 16);
    float h1 = __uint_as_float(hp & 0xFFFF0000u);
    lp = cvt_bf16x2(f0 - h0, f1 - h1);
}

// ---------------------------- w split kernel --------------------------------
__global__ void split_w_kernel(const float4* __restrict__ w4) {
    uint2* oh = reinterpret_cast<uint2*>(g_whi);
    uint2* ol = reinterpret_cast<uint2*>(g_wlo);
    const int n4 = (N_DIM * K_DIM) / 4;
    for (int i = blockIdx.x * blockDim.x + threadIdx.x; i < n4;
         i += gridDim.x * blockDim.x) {
        float4 v = w4[i];
        uint2 h, l;
        split_pair(v.x, v.y, h.x, l.x);
        split_pair(v.z, v.w, h.y, l.y);
        oh[i] = h; ol[i] = l;
    }
}

// ---------------------------- GEMM kernel -----------------------------------
// Per-stage SMEM: XH(16K) XL(16K) WH(16K) WL(16K); SW128 swizzle per tile:
// byte = row*128 + ((c16 ^ (row&7)) << 4), row = m-or-n row, c16 = 16B chunk.

__device__ __forceinline__ void load_w(uint32_t sbase, int s, int kc,
                                       int n_base, int tid) {
    const uint32_t base = sbase + (uint32_t)s * STAGE_BYTES + 2u * TILE_SZ;
    const int kcol = kc * KC;
#pragma unroll
    for (int i = 0; i < 4; i++) {          // 1024 chunks / 256 threads
        int idx = tid + i * 256;
        int row = idx >> 3, c16 = idx & 7;
        uint32_t d0 = base + (uint32_t)row * 128u +
                      (uint32_t)((c16 ^ (row & 7)) << 4);
        size_t off = (size_t)(n_base + row) * K_DIM + kcol + c16 * 8;
        cp16(d0, g_whi + off);
        cp16(d0 + TILE_SZ, g_wlo + off);
    }
}

__device__ __forceinline__ void ldg_x(const float* __restrict__ x, int kc,
                                      int m_base, int tid, float4 xf[4][2]) {
    const int kcol = kc * KC;
#pragma unroll
    for (int i = 0; i < 4; i++) {
        int idx = tid + i * 256;
        int row = idx >> 3, c16 = idx & 7;
        const float* p = x + (size_t)(m_base + row) * K_DIM + kcol + c16 * 8;
        xf[i][0] = *reinterpret_cast<const float4*>(p);
        xf[i][1] = *reinterpret_cast<const float4*>(p + 4);
    }
}

__device__ __forceinline__ void store_x(uint32_t sbase, int s, int tid,
                                        const float4 xf[4][2]) {
    const uint32_t xh = sbase + (uint32_t)s * STAGE_BYTES;
#pragma unroll
    for (int i = 0; i < 4; i++) {
        int idx = tid + i * 256;
        int row = idx >> 3, c16 = idx & 7;
        const float* f = (const float*)&xf[i][0];
        uint4 hv, lv;
        split_pair(f[0], f[1], hv.x, lv.x);
        split_pair(f[2], f[3], hv.y, lv.y);
        split_pair(f[4], f[5], hv.z, lv.z);
        split_pair(f[6], f[7], hv.w, lv.w);
        uint32_t d0 = xh + (uint32_t)row * 128u +
                      (uint32_t)((c16 ^ (row & 7)) << 4);
        sts16(d0, hv);
        sts16(d0 + TILE_SZ, lv);
    }
}

// one K=16 step of MMAs over stage tiles
__device__ __forceinline__ void mma_kstep(uint32_t xh, uint32_t xl,
                                          uint32_t wh, uint32_t wl, int ks,
                                          int a_row, int a_ks, int b_row,
                                          int b_ks, float acc[2][8][4]) {
    uint32_t ah[2][4], al[2][4], bh[8][2], bl[8][2];
#pragma unroll
    for (int mt = 0; mt < 2; mt++) {
        int r = a_row + mt * 16;
        int c16 = ks * 2 + a_ks;
        uint32_t off = (uint32_t)r * 128u + (uint32_t)((c16 ^ (r & 7)) << 4);
        ldsm_x4(xh + off, ah[mt][0], ah[mt][1], ah[mt][2], ah[mt][3]);
        ldsm_x4(xl + off, al[mt][0], al[mt][1], al[mt][2], al[mt][3]);
    }
#pragma unroll
    for (int bt = 0; bt < 4; bt++) {
        int r = b_row + bt * 16;
        int c16 = ks * 2 + b_ks;
        uint32_t off = (uint32_t)r * 128u + (uint32_t)((c16 ^ (r & 7)) << 4);
        ldsm_x4(wh + off, bh[2 * bt][0], bh[2 * bt][1],
                bh[2 * bt + 1][0], bh[2 * bt + 1][1]);
        ldsm_x4(wl + off, bl[2 * bt][0], bl[2 * bt][1],
                bl[2 * bt + 1][0], bl[2 * bt + 1][1]);
    }
#pragma unroll
    for (int mt = 0; mt < 2; mt++)
#pragma unroll
        for (int nt = 0; nt < 8; nt++)
            mma16816(acc[mt][nt], ah[mt], bh[nt]);   // hh
#pragma unroll
    for (int mt = 0; mt < 2; mt++)
#pragma unroll
        for (int nt = 0; nt < 8; nt++)
            mma16816(acc[mt][nt], ah[mt], bl[nt]);   // hl
#pragma unroll
    for (int mt = 0; mt < 2; mt++)
#pragma unroll
        for (int nt = 0; nt < 8; nt++)
            mma16816(acc[mt][nt], al[mt], bh[nt]);   // lh
}

__global__ void __launch_bounds__(256, 1)
gemm_bf16x3_kernel(const float* __restrict__ x, float* __restrict__ y) {
    extern __shared__ char smem[];
    const uint32_t sbase = smem_u32(smem);
    const int tid = threadIdx.x;
    const int wid = tid >> 5;
    const int lid = tid & 31;
    const int m_base = blockIdx.y * MT;
    const int n_base = blockIdx.x * NT;

    const int wm = wid >> 1;   // warp -> 32 M rows
    const int wn = wid & 1;    // warp -> 64 N cols

    float acc[2][8][4];
#pragma unroll
    for (int mt = 0; mt < 2; mt++)
#pragma unroll
        for (int nt = 0; nt < 8; nt++)
#pragma unroll
            for (int j = 0; j < 4; j++) acc[mt][nt][j] = 0.f;

    // ldmatrix lane addressing (PTX fragment layouts):
    const int a_row = wm * 32 + (lid & 15);
    const int a_ks = lid >> 4;
    const int b_row = wn * 64 + ((lid >> 4) << 3) + (lid & 7);
    const int b_ks = (lid >> 3) & 1;

    float4 xf[4][2];

    // ---- prologue: fill stage 0 with chunk 0 ----
    ldg_x(x, 0, m_base, tid, xf);
    store_x(sbase, 0, tid, xf);
    load_w(sbase, 0, 0, n_base, tid);
    CP_COMMIT();
    asm volatile("cp.async.wait_group 0;" ::: "memory");
    __syncthreads();

#pragma unroll 1
    for (int c = 0; c < NCHUNK; c++) {
        const int s = c & 1;
        const int f = s ^ 1;
        const bool more = (c + 1 < NCHUNK);

        if (more) {
            ldg_x(x, c + 1, m_base, tid, xf);   // long-latency; consumed mid-MMA
            load_w(sbase, f, c + 1, n_base, tid);
            CP_COMMIT();
        }

        const uint32_t xh = sbase + (uint32_t)s * STAGE_BYTES;
        const uint32_t xl = xh + TILE_SZ;
        const uint32_t wh = xh + 2u * TILE_SZ;
        const uint32_t wl = xh + 3u * TILE_SZ;

        mma_kstep(xh, xl, wh, wl, 0, a_row, a_ks, b_row, b_ks, acc);
        mma_kstep(xh, xl, wh, wl, 1, a_row, a_ks, b_row, b_ks, acc);

        if (more) store_x(sbase, f, tid, xf);   // overlap split/STS with MMAs

        mma_kstep(xh, xl, wh, wl, 2, a_row, a_ks, b_row, b_ks, acc);
        mma_kstep(xh, xl, wh, wl, 3, a_row, a_ks, b_row, b_ks, acc);

        if (more)
            asm volatile("cp.async.wait_group 0;" ::: "memory");
        __syncthreads();   // end of reads of stage s; stage f fills visible
    }

    // ---- epilogue: direct float2 stores ----
    const int mrow0 = m_base + wm * 32 + (lid >> 2);
    const int ncol0 = n_base + wn * 64 + (lid & 3) * 2;
#pragma unroll
    for (int mt = 0; mt < 2; mt++) {
#pragma unroll
        for (int nt = 0; nt < 8; nt++) {
            float2 v0 = make_float2(acc[mt][nt][0], acc[mt][nt][1]);
            float2 v1 = make_float2(acc[mt][nt][2], acc[mt][nt][3]);
            size_t r0 = (size_t)(mrow0 + mt * 16) * N_DIM + ncol0 + nt * 8;
            size_t r1 = (size_t)(mrow0 + mt * 16 + 8) * N_DIM + ncol0 + nt * 8;
            *reinterpret_cast<float2*>(&y[r0]) = v0;
            *reinterpret_cast<float2*>(&y[r1]) = v1;
        }
    }
}

// ---------------------------- launch ----------------------------------------
extern "C" void kernel_launch(void* const* d_in, const int* in_sizes, int n_in,
                              void* d_out, int out_size) {
    const float* x = (const float*)d_in[0];   // 65536 x 512 f32
    const float* w = (const float*)d_in[1];   // 512 x 512 f32 (row-major A)
    float* y = (float*)d_out;

    cudaFuncSetAttribute(gemm_bf16x3_kernel,
                         cudaFuncAttributeMaxDynamicSharedMemorySize,
                         (int)SMEM_BYTES);

    split_w_kernel<<<64, 256>>>(reinterpret_cast<const float4*>(w));

    dim3 grid(N_DIM / NT, M_TOTAL / MT);  // (4, 512)
    gemm_bf16x3_kernel<<<grid, 256, SMEM_BYTES>>>(x, y);
}